// round 13
// baseline (speedup 1.0000x reference)
#include <cuda_runtime.h>
#include <cuda_fp16.h>
#include <cstdint>

#define NNODES 10000
#define NEDGES 160000
#define FDIM   512
#define NGRAPH 64
#define ODIM   128
#define ELLW   64

// Scratch (device globals; no allocation allowed)
__device__ __half g_x16[NNODES * FDIM];     // fp16 input features
__device__ __half g_w1t[FDIM * FDIM];       // W1 transposed [N][K] fp16
__device__ __half g_w2t[FDIM * FDIM];       // W2 transposed [N][K] fp16
__device__ __half g_a16[NNODES * FDIM];     // gemm output (pre-agg)
__device__ __half g_b16[NNODES * FDIM];     // agg1 output (layer-2 input)
__device__ float  g_buf2[NNODES * FDIM];    // agg2 fp32 output (for pool)
__device__ int    g_cnt[NNODES];
__device__ int2   g_ell2[NNODES * ELLW];    // (src, nrm bits)
__device__ float  g_pooled[NGRAPH * FDIM];

__device__ __forceinline__ int clampi(int v, int lo, int hi) {
    return v < lo ? lo : (v > hi ? hi : v);
}

__device__ __forceinline__ void mma_f16(float* c, const uint32_t* a, const uint32_t* b) {
    asm volatile(
        "mma.sync.aligned.m16n8k16.row.col.f32.f16.f16.f32 "
        "{%0,%1,%2,%3}, {%4,%5,%6,%7}, {%8,%9}, {%0,%1,%2,%3};"
        : "+f"(c[0]), "+f"(c[1]), "+f"(c[2]), "+f"(c[3])
        : "r"(a[0]), "r"(a[1]), "r"(a[2]), "r"(a[3]), "r"(b[0]), "r"(b[1]));
}

__device__ __forceinline__ void ldsm_x4(uint32_t* r, uint32_t addr) {
    asm volatile(
        "ldmatrix.sync.aligned.m8n8.x4.shared.b16 {%0,%1,%2,%3}, [%4];"
        : "=r"(r[0]), "=r"(r[1]), "=r"(r[2]), "=r"(r[3]) : "r"(addr));
}

// ---------------------------------------------------------------------------
// Fused convert + cnt-zero, block-range dispatch
// ---------------------------------------------------------------------------
#define XBLK   (NNODES * FDIM / 4 / 256)        // 5000
#define WTILES (FDIM / 32 * FDIM / 32)          // 256 per weight
#define CBLK   ((NNODES + 255) / 256)           // 40
#define CONVERT_GRID (XBLK + 2 * WTILES + CBLK)

__global__ void convert_zero_kernel(const float* __restrict__ x,
                                    const float* __restrict__ W1,
                                    const float* __restrict__ W2,
                                    __half* __restrict__ x16,
                                    __half* __restrict__ w1t,
                                    __half* __restrict__ w2t,
                                    int* __restrict__ cnt) {
    int b = blockIdx.x;
    int tid = threadIdx.x;
    if (b < XBLK) {
        int i = b * 256 + tid;
        float4 v = ((const float4*)x)[i];
        __half2 h0 = __floats2half2_rn(v.x, v.y);
        __half2 h1 = __floats2half2_rn(v.z, v.w);
        uint2 u;
        u.x = *(uint32_t*)&h0; u.y = *(uint32_t*)&h1;
        ((uint2*)x16)[i] = u;
    } else if (b < XBLK + 2 * WTILES) {
        __shared__ float tile[32][33];
        int wi = b - XBLK;
        const float* W = (wi < WTILES) ? W1 : W2;
        __half* Wt = (wi < WTILES) ? w1t : w2t;
        int t = wi & (WTILES - 1);
        int k0 = (t >> 4) * 32;
        int n0 = (t & 15) * 32;
        int tx = tid & 31;
        int ty = tid >> 5;          // 0..7
#pragma unroll
        for (int i = ty; i < 32; i += 8)
            tile[i][tx] = W[(size_t)(k0 + i) * FDIM + n0 + tx];
        __syncthreads();
#pragma unroll
        for (int i = ty; i < 32; i += 8)
            Wt[(size_t)(n0 + i) * FDIM + k0 + tx] = __float2half_rn(tile[tx][i]);
    } else {
        int i = (b - XBLK - 2 * WTILES) * 256 + tid;
        if (i < NNODES) cnt[i] = 0;
    }
}

// ---------------------------------------------------------------------------
// ELL scatter (fills .x = src), then nrm pass (fills .y after cnt final)
// ---------------------------------------------------------------------------
__global__ void scatter_ell_kernel(const int* __restrict__ src, const int* __restrict__ dst,
                                   int* cnt, int2* ell2, int e) {
    int i = blockIdx.x * blockDim.x + threadIdx.x;
    if (i >= e) return;
    int d = clampi(dst[i], 0, NNODES - 1);
    int s = clampi(src[i], 0, NNODES - 1);
    int slot = atomicAdd(&cnt[d], 1);
    if (slot < ELLW) ell2[d * ELLW + slot].x = s;
}

__global__ void nrm_kernel(const int* __restrict__ cnt, int2* __restrict__ ell2) {
    int i = blockIdx.x * blockDim.x + threadIdx.x;
    if (i >= NNODES * ELLW) return;
    int d = i >> 6;
    int slot = i & (ELLW - 1);
    int cd = cnt[d];
    if (slot >= min(cd, ELLW)) return;
    int s = ell2[i].x;
    float nrm = rsqrtf((float)(cnt[s] + 1)) * rsqrtf((float)(cd + 1));
    ell2[i].y = __float_as_int(nrm);
}

// ---------------------------------------------------------------------------
// fp16 tensor-core GEMM with ldmatrix fragment loads.
// C16[M,512] = A16[M,512] @ Bt16[512,512]^T, fp32 accum.
// 128x128 tile, BK=32, 8 warps (2x4), warp tile 64x32, m16n8k16.
// ---------------------------------------------------------------------------
__global__ void __launch_bounds__(256, 2)
h16_gemm_kernel(const __half* __restrict__ A, const __half* __restrict__ Bt,
                __half* __restrict__ C16, int M) {
    const int K = FDIM, N = FDIM, BK = 32;
    const int PITCH = BK + 8;                       // 40 halves = 80B row
    __shared__ __half As[2][128][PITCH];
    __shared__ __half Bs[2][128][PITCH];

    int tid = threadIdx.x;
    int lane = tid & 31;
    int wid = tid >> 5;
    int warp_m = wid >> 2;       // 0..1
    int warp_n = wid & 3;        // 0..3

    int bm = blockIdx.y * 128;
    int bn = blockIdx.x * 128;

    int lrow = tid >> 1;         // 0..127
    int lcol = (tid & 1) * 16;   // halves: 0 or 16

    float acc[4][4][4] = {};
    uint4 a_pre[2], b_pre[2];

    const int T = K / BK;        // 16
    const uint32_t BUF = 128 * PITCH * 2;   // bytes per buffer

    uint32_t as_base = (uint32_t)__cvta_generic_to_shared(&As[0][0][0]);
    uint32_t bs_base = (uint32_t)__cvta_generic_to_shared(&Bs[0][0][0]);

    // ldmatrix lane offsets (bytes)
    // A x4: lanes 0-15 -> row (warp_m*64 + lane&15), col +0 ; lanes 16-31 -> same row set, col +8
    uint32_t a_lane = ((warp_m * 64 + (lane & 15)) * PITCH + ((lane >> 4) * 8)) * 2;
    // B x4 (two n-tiles): lanes 0-7 rows n0+0..7 col 0; 8-15 rows n0+0..7 col 8;
    //                     16-23 rows n0+8..15 col 0; 24-31 rows n0+8..15 col 8
    uint32_t b_lane = ((warp_n * 32 + (lane & 7) + (((lane >> 4) & 1) * 8)) * PITCH
                       + (((lane >> 3) & 1) * 8)) * 2;

    // prefetch tile 0
    {
        int gr = bm + lrow;
        a_pre[0] = make_uint4(0, 0, 0, 0);
        a_pre[1] = make_uint4(0, 0, 0, 0);
        if (gr < M) {
            a_pre[0] = *(const uint4*)(A + (size_t)gr * K + lcol);
            a_pre[1] = *(const uint4*)(A + (size_t)gr * K + lcol + 8);
        }
        b_pre[0] = *(const uint4*)(Bt + (size_t)(bn + lrow) * K + lcol);
        b_pre[1] = *(const uint4*)(Bt + (size_t)(bn + lrow) * K + lcol + 8);
        *(uint4*)&As[0][lrow][lcol]     = a_pre[0];
        *(uint4*)&As[0][lrow][lcol + 8] = a_pre[1];
        *(uint4*)&Bs[0][lrow][lcol]     = b_pre[0];
        *(uint4*)&Bs[0][lrow][lcol + 8] = b_pre[1];
    }
    __syncthreads();

    for (int t = 0; t < T; t++) {
        int cur = t & 1;
        int nxt = cur ^ 1;
        if (t + 1 < T) {
            int k0 = (t + 1) * BK;
            int gr = bm + lrow;
            a_pre[0] = make_uint4(0, 0, 0, 0);
            a_pre[1] = make_uint4(0, 0, 0, 0);
            if (gr < M) {
                a_pre[0] = *(const uint4*)(A + (size_t)gr * K + k0 + lcol);
                a_pre[1] = *(const uint4*)(A + (size_t)gr * K + k0 + lcol + 8);
            }
            b_pre[0] = *(const uint4*)(Bt + (size_t)(bn + lrow) * K + k0 + lcol);
            b_pre[1] = *(const uint4*)(Bt + (size_t)(bn + lrow) * K + k0 + lcol + 8);
        }

        uint32_t abase = as_base + cur * BUF + a_lane;
        uint32_t bbase = bs_base + cur * BUF + b_lane;

#pragma unroll
        for (int ks = 0; ks < BK; ks += 16) {
            uint32_t af[4][4], bf[4][2];
#pragma unroll
            for (int mi = 0; mi < 4; mi++)
                ldsm_x4(af[mi], abase + (mi * 16 * PITCH + ks) * 2);
#pragma unroll
            for (int np = 0; np < 2; np++) {
                uint32_t r[4];
                ldsm_x4(r, bbase + (np * 16 * PITCH + ks) * 2);
                bf[np * 2][0] = r[0]; bf[np * 2][1] = r[1];
                bf[np * 2 + 1][0] = r[2]; bf[np * 2 + 1][1] = r[3];
            }
#pragma unroll
            for (int mi = 0; mi < 4; mi++)
#pragma unroll
                for (int ni = 0; ni < 4; ni++)
                    mma_f16(acc[mi][ni], af[mi], bf[ni]);
        }

        if (t + 1 < T) {
            *(uint4*)&As[nxt][lrow][lcol]     = a_pre[0];
            *(uint4*)&As[nxt][lrow][lcol + 8] = a_pre[1];
            *(uint4*)&Bs[nxt][lrow][lcol]     = b_pre[0];
            *(uint4*)&Bs[nxt][lrow][lcol + 8] = b_pre[1];
        }
        __syncthreads();
    }

    // epilogue: fp16 store
    int col_in_frag = (lane & 3) * 2;
#pragma unroll
    for (int mi = 0; mi < 4; mi++) {
#pragma unroll
        for (int ni = 0; ni < 4; ni++) {
            int r0 = bm + warp_m * 64 + mi * 16 + (lane >> 2);
            int c0 = bn + warp_n * 32 + ni * 8 + col_in_frag;
            if (r0 < M) {
                __half2 h = __floats2half2_rn(acc[mi][ni][0], acc[mi][ni][1]);
                *(__half2*)(C16 + (size_t)r0 * N + c0) = h;
            }
            if (r0 + 8 < M) {
                __half2 h = __floats2half2_rn(acc[mi][ni][2], acc[mi][ni][3]);
                *(__half2*)(C16 + (size_t)(r0 + 8) * N + c0) = h;
            }
        }
    }
}

// ---------------------------------------------------------------------------
// Fused aggregation (fp16 gather, precomputed edge norms)
// ---------------------------------------------------------------------------
__global__ void __launch_bounds__(128)
fused_agg_kernel(const __half* __restrict__ h16, const int* __restrict__ cnt,
                 const int2* __restrict__ ell2, const float* __restrict__ bias,
                 __half* __restrict__ out16, float* __restrict__ out32,
                 int write16, int write32) {
    int grp  = threadIdx.x >> 6;          // 0..1
    int lane = threadIdx.x & 63;          // owns halves [lane*8, lane*8+8)
    int d = blockIdx.x * 2 + grp;

    int cd = cnt[d];
    float dd = rsqrtf((float)(cd + 1));
    int deg = min(cd, ELLW);
    const int2* erow = ell2 + (size_t)d * ELLW;

    float4 sp = ((const float4*)(h16 + (size_t)d * FDIM))[lane];
    const __half2* sh = (const __half2*)&sp;
    float sdd = dd * dd;
    float2 s0 = __half22float2(sh[0]);
    float2 s1 = __half22float2(sh[1]);
    float2 s2 = __half22float2(sh[2]);
    float2 s3 = __half22float2(sh[3]);
    float acc[8] = { s0.x * sdd, s0.y * sdd, s1.x * sdd, s1.y * sdd,
                     s2.x * sdd, s2.y * sdd, s3.x * sdd, s3.y * sdd };

#pragma unroll 2
    for (int j = 0; j < deg; j++) {
        int2 e = erow[j];                       // 8B broadcast: (src, nrm)
        int s = e.x;
        float nrm = __int_as_float(e.y);
        float4 p = ((const float4*)(h16 + (size_t)s * FDIM))[lane];
        const __half2* hp = (const __half2*)&p;
        float2 f0 = __half22float2(hp[0]);
        float2 f1 = __half22float2(hp[1]);
        float2 f2 = __half22float2(hp[2]);
        float2 f3 = __half22float2(hp[3]);
        acc[0] += f0.x * nrm; acc[1] += f0.y * nrm;
        acc[2] += f1.x * nrm; acc[3] += f1.y * nrm;
        acc[4] += f2.x * nrm; acc[5] += f2.y * nrm;
        acc[6] += f3.x * nrm; acc[7] += f3.y * nrm;
    }

    const float4* brow = (const float4*)bias;
    float4 b0 = brow[lane * 2];
    float4 b1 = brow[lane * 2 + 1];
    float v[8];
    v[0] = fmaxf(acc[0] + b0.x, 0.f); v[1] = fmaxf(acc[1] + b0.y, 0.f);
    v[2] = fmaxf(acc[2] + b0.z, 0.f); v[3] = fmaxf(acc[3] + b0.w, 0.f);
    v[4] = fmaxf(acc[4] + b1.x, 0.f); v[5] = fmaxf(acc[5] + b1.y, 0.f);
    v[6] = fmaxf(acc[6] + b1.z, 0.f); v[7] = fmaxf(acc[7] + b1.w, 0.f);

    if (write16) {
        __half2 h0 = __floats2half2_rn(v[0], v[1]);
        __half2 h1 = __floats2half2_rn(v[2], v[3]);
        __half2 h2 = __floats2half2_rn(v[4], v[5]);
        __half2 h3 = __floats2half2_rn(v[6], v[7]);
        uint4 u;
        u.x = *(uint32_t*)&h0; u.y = *(uint32_t*)&h1;
        u.z = *(uint32_t*)&h2; u.w = *(uint32_t*)&h3;
        ((uint4*)(out16 + (size_t)d * FDIM))[lane] = u;
    }
    if (write32) {
        float4* orow = (float4*)(out32 + (size_t)d * FDIM);
        orow[lane * 2]     = make_float4(v[0], v[1], v[2], v[3]);
        orow[lane * 2 + 1] = make_float4(v[4], v[5], v[6], v[7]);
    }
}

// ---------------------------------------------------------------------------
// Pooling (batch sorted): grid (graph, 4 strips), binary-search node range
// ---------------------------------------------------------------------------
__global__ void __launch_bounds__(128)
pool_kernel(const float* __restrict__ h, const int* __restrict__ batch,
            float* __restrict__ pooled) {
    int g = blockIdx.x;
    int f = blockIdx.y * 128 + threadIdx.x;

    int lo = 0, hi = NNODES;
    while (lo < hi) { int mid = (lo + hi) >> 1; if (batch[mid] < g) lo = mid + 1; else hi = mid; }
    int beg = lo;
    hi = NNODES;
    while (lo < hi) { int mid = (lo + hi) >> 1; if (batch[mid] < g + 1) lo = mid + 1; else hi = mid; }
    int end = lo;

    float acc = 0.f;
    for (int n = beg; n < end; n++)
        acc += h[(size_t)n * FDIM + f];
    pooled[g * FDIM + f] = acc;
}

// ---------------------------------------------------------------------------
// Final small GEMM: out[64,128] = pooled[64,512] @ Wlin[512,128] + blin
// ---------------------------------------------------------------------------
__global__ void __launch_bounds__(128)
final_gemm_kernel(const float* __restrict__ pooled,
                  const float* __restrict__ Wlin,
                  const float* __restrict__ blin,
                  float* __restrict__ out) {
    __shared__ float p[FDIM];
    int g = blockIdx.x;
    int o = threadIdx.x;   // 128
    for (int k = o; k < FDIM; k += ODIM) p[k] = pooled[g * FDIM + k];
    __syncthreads();
    float acc = blin[o];
#pragma unroll 8
    for (int k = 0; k < FDIM; k++) acc += p[k] * Wlin[k * ODIM + o];
    out[g * ODIM + o] = acc;
}

// ---------------------------------------------------------------------------
// Launch
// ---------------------------------------------------------------------------
extern "C" void kernel_launch(void* const* d_in, const int* in_sizes, int n_in,
                              void* d_out, int out_size) {
    const float* x    = (const float*)d_in[0];
    const float* W1   = (const float*)d_in[1];
    const float* b1   = (const float*)d_in[2];
    const float* W2   = (const float*)d_in[3];
    const float* b2   = (const float*)d_in[4];
    const float* Wlin = (const float*)d_in[5];
    const float* blin = (const float*)d_in[6];
    const int* edge_index = (const int*)d_in[7];   // harness maps int64 -> int32
    const int* batch      = (const int*)d_in[8];

    const int* src = edge_index;
    const int* dst = edge_index + NEDGES;

    __half *x16, *w1t, *w2t, *a16, *b16;
    float *buf2, *pooled_scratch;
    int *cnt;
    int2 *ell2;
    cudaGetSymbolAddress((void**)&x16, g_x16);
    cudaGetSymbolAddress((void**)&w1t, g_w1t);
    cudaGetSymbolAddress((void**)&w2t, g_w2t);
    cudaGetSymbolAddress((void**)&a16, g_a16);
    cudaGetSymbolAddress((void**)&b16, g_b16);
    cudaGetSymbolAddress((void**)&buf2, g_buf2);
    cudaGetSymbolAddress((void**)&pooled_scratch, g_pooled);
    cudaGetSymbolAddress((void**)&cnt, g_cnt);
    cudaGetSymbolAddress((void**)&ell2, g_ell2);

    float* pooled;
    float* out2;
    if (out_size >= NGRAPH * FDIM + NGRAPH * ODIM) {
        pooled = (float*)d_out;
        out2   = (float*)d_out + NGRAPH * FDIM;
    } else {
        pooled = pooled_scratch;
        out2   = (float*)d_out;
    }

    // Side stream: scatter + nrm overlapped with GEMM1 (capturable fork/join).
    static cudaStream_t side = nullptr;
    static cudaEvent_t evFork = nullptr, evJoin = nullptr;
    static bool inited = false;
    if (!inited) {
        inited = true;
        if (cudaStreamCreateWithFlags(&side, cudaStreamNonBlocking) != cudaSuccess)
            side = nullptr;
        if (side) {
            if (cudaEventCreateWithFlags(&evFork, cudaEventDisableTiming) != cudaSuccess ||
                cudaEventCreateWithFlags(&evJoin, cudaEventDisableTiming) != cudaSuccess)
                side = nullptr;
        }
    }

    dim3 gemm_grid(FDIM / 128, (NNODES + 127) / 128);

    // 1. convert + transpose + zero cnt (single launch)
    convert_zero_kernel<<<CONVERT_GRID, 256>>>(x, W1, W2, x16, w1t, w2t, cnt);

    if (side) {
        cudaEventRecord(evFork, 0);
        cudaStreamWaitEvent(side, evFork, 0);
        scatter_ell_kernel<<<(NEDGES + 255) / 256, 256, 0, side>>>(src, dst, cnt, ell2, NEDGES);
        nrm_kernel<<<(NNODES * ELLW + 255) / 256, 256, 0, side>>>(cnt, ell2);
        cudaEventRecord(evJoin, side);
        h16_gemm_kernel<<<gemm_grid, 256>>>(x16, w1t, a16, NNODES);
        cudaStreamWaitEvent(0, evJoin, 0);
    } else {
        scatter_ell_kernel<<<(NEDGES + 255) / 256, 256>>>(src, dst, cnt, ell2, NEDGES);
        nrm_kernel<<<(NNODES * ELLW + 255) / 256, 256>>>(cnt, ell2);
        h16_gemm_kernel<<<gemm_grid, 256>>>(x16, w1t, a16, NNODES);
    }

    // agg1
    fused_agg_kernel<<<NNODES / 2, 128>>>(a16, cnt, ell2, b1, b16, nullptr, 1, 0);

    // Layer 2
    h16_gemm_kernel<<<gemm_grid, 256>>>(b16, w2t, a16, NNODES);
    fused_agg_kernel<<<NNODES / 2, 128>>>(a16, cnt, ell2, b2, nullptr, buf2, 0, 1);

    // Pool + final linear
    {
        dim3 pg(NGRAPH, FDIM / 128);
        pool_kernel<<<pg, 128>>>(buf2, batch, pooled);
    }
    final_gemm_kernel<<<NGRAPH, ODIM>>>(pooled, Wlin, blin, out2);
}

// round 14
// speedup vs baseline: 1.0614x; 1.0614x over previous
#include <cuda_runtime.h>
#include <cuda_fp16.h>
#include <cstdint>

#define NNODES 10000
#define NEDGES 160000
#define FDIM   512
#define NGRAPH 64
#define ODIM   128
#define ELLW   64

// Scratch (device globals; no allocation allowed)
__device__ __half g_x16[NNODES * FDIM];     // fp16 input features
__device__ __half g_w1t[FDIM * FDIM];       // W1 transposed [N][K] fp16
__device__ __half g_w2t[FDIM * FDIM];       // W2 transposed [N][K] fp16
__device__ __half g_a16[NNODES * FDIM];     // gemm output (pre-agg)
__device__ __half g_b16[NNODES * FDIM];     // agg1 output (layer-2 input)
__device__ float  g_buf2[NNODES * FDIM];    // agg2 fp32 output (for pool)
__device__ int    g_cnt[NNODES];
__device__ int2   g_ell2[NNODES * ELLW];    // (src, nrm bits)
__device__ float  g_pooled[NGRAPH * FDIM];

__device__ __forceinline__ int clampi(int v, int lo, int hi) {
    return v < lo ? lo : (v > hi ? hi : v);
}

__device__ __forceinline__ void mma_f16(float* c, const uint32_t* a, const uint32_t* b) {
    asm volatile(
        "mma.sync.aligned.m16n8k16.row.col.f32.f16.f16.f32 "
        "{%0,%1,%2,%3}, {%4,%5,%6,%7}, {%8,%9}, {%0,%1,%2,%3};"
        : "+f"(c[0]), "+f"(c[1]), "+f"(c[2]), "+f"(c[3])
        : "r"(a[0]), "r"(a[1]), "r"(a[2]), "r"(a[3]), "r"(b[0]), "r"(b[1]));
}

__device__ __forceinline__ void ldsm_x4(uint32_t* r, uint32_t addr) {
    asm volatile(
        "ldmatrix.sync.aligned.m8n8.x4.shared.b16 {%0,%1,%2,%3}, [%4];"
        : "=r"(r[0]), "=r"(r[1]), "=r"(r[2]), "=r"(r[3]) : "r"(addr));
}

__device__ __forceinline__ void cp_async16(uint32_t smem_dst, const void* gmem_src) {
    asm volatile("cp.async.cg.shared.global [%0], [%1], 16;\n"
                 :: "r"(smem_dst), "l"(gmem_src) : "memory");
}
__device__ __forceinline__ void cp_commit() {
    asm volatile("cp.async.commit_group;\n" ::: "memory");
}
template <int N>
__device__ __forceinline__ void cp_wait() {
    asm volatile("cp.async.wait_group %0;\n" :: "n"(N) : "memory");
}

// ---------------------------------------------------------------------------
// Fused convert + cnt-zero, block-range dispatch
// ---------------------------------------------------------------------------
#define XBLK   (NNODES * FDIM / 4 / 256)        // 5000
#define WTILES (FDIM / 32 * FDIM / 32)          // 256 per weight
#define CBLK   ((NNODES + 255) / 256)           // 40
#define CONVERT_GRID (XBLK + 2 * WTILES + CBLK)

__global__ void convert_zero_kernel(const float* __restrict__ x,
                                    const float* __restrict__ W1,
                                    const float* __restrict__ W2,
                                    __half* __restrict__ x16,
                                    __half* __restrict__ w1t,
                                    __half* __restrict__ w2t,
                                    int* __restrict__ cnt) {
    int b = blockIdx.x;
    int tid = threadIdx.x;
    if (b < XBLK) {
        int i = b * 256 + tid;
        float4 v = ((const float4*)x)[i];
        __half2 h0 = __floats2half2_rn(v.x, v.y);
        __half2 h1 = __floats2half2_rn(v.z, v.w);
        uint2 u;
        u.x = *(uint32_t*)&h0; u.y = *(uint32_t*)&h1;
        ((uint2*)x16)[i] = u;
    } else if (b < XBLK + 2 * WTILES) {
        __shared__ float tile[32][33];
        int wi = b - XBLK;
        const float* W = (wi < WTILES) ? W1 : W2;
        __half* Wt = (wi < WTILES) ? w1t : w2t;
        int t = wi & (WTILES - 1);
        int k0 = (t >> 4) * 32;
        int n0 = (t & 15) * 32;
        int tx = tid & 31;
        int ty = tid >> 5;          // 0..7
#pragma unroll
        for (int i = ty; i < 32; i += 8)
            tile[i][tx] = W[(size_t)(k0 + i) * FDIM + n0 + tx];
        __syncthreads();
#pragma unroll
        for (int i = ty; i < 32; i += 8)
            Wt[(size_t)(n0 + i) * FDIM + k0 + tx] = __float2half_rn(tile[tx][i]);
    } else {
        int i = (b - XBLK - 2 * WTILES) * 256 + tid;
        if (i < NNODES) cnt[i] = 0;
    }
}

// ---------------------------------------------------------------------------
// ELL scatter (fills .x = src), then nrm pass (fills .y after cnt final)
// ---------------------------------------------------------------------------
__global__ void scatter_ell_kernel(const int* __restrict__ src, const int* __restrict__ dst,
                                   int* cnt, int2* ell2, int e) {
    int i = blockIdx.x * blockDim.x + threadIdx.x;
    if (i >= e) return;
    int d = clampi(dst[i], 0, NNODES - 1);
    int s = clampi(src[i], 0, NNODES - 1);
    int slot = atomicAdd(&cnt[d], 1);
    if (slot < ELLW) ell2[d * ELLW + slot].x = s;
}

__global__ void nrm_kernel(const int* __restrict__ cnt, int2* __restrict__ ell2) {
    int i = blockIdx.x * blockDim.x + threadIdx.x;
    if (i >= NNODES * ELLW) return;
    int d = i >> 6;
    int slot = i & (ELLW - 1);
    int cd = cnt[d];
    if (slot >= min(cd, ELLW)) return;
    int s = ell2[i].x;
    float nrm = rsqrtf((float)(cnt[s] + 1)) * rsqrtf((float)(cd + 1));
    ell2[i].y = __float_as_int(nrm);
}

// ---------------------------------------------------------------------------
// fp16 tensor-core GEMM: 4-stage cp.async pipeline + ldmatrix.
// C16[M,512] = A16[M,512] @ Bt16[512,512]^T, fp32 accum.
// 128x128 tile, BK=32, 8 warps (2x4), warp tile 64x32, m16n8k16.
// Dynamic smem: 4 stages x (A 10240B + B 10240B) = 81920B.
// ---------------------------------------------------------------------------
#define GEMM_BK     32
#define GEMM_PITCH  40                          // halves per row (80B)
#define GEMM_ABUF   (128 * GEMM_PITCH * 2)      // bytes per stage per operand
#define GEMM_STAGES 4
#define GEMM_SMEM   (2 * GEMM_STAGES * GEMM_ABUF)   // 81920

__global__ void __launch_bounds__(256, 2)
h16_gemm_kernel(const __half* __restrict__ A, const __half* __restrict__ Bt,
                __half* __restrict__ C16, int M) {
    const int K = FDIM, N = FDIM, BK = GEMM_BK;
    const int PITCH = GEMM_PITCH;
    extern __shared__ __half smem[];

    int tid = threadIdx.x;
    int lane = tid & 31;
    int wid = tid >> 5;
    int warp_m = wid >> 2;       // 0..1
    int warp_n = wid & 3;        // 0..3

    int bm = blockIdx.y * 128;
    int bn = blockIdx.x * 128;

    int lrow = tid >> 1;         // 0..127
    int lcol = (tid & 1) * 16;   // halves: 0 or 16

    float acc[4][4][4] = {};

    const int T = K / BK;        // 16

    uint32_t as_base = (uint32_t)__cvta_generic_to_shared(smem);
    uint32_t bs_base = as_base + GEMM_STAGES * GEMM_ABUF;
    uint32_t st_off = (lrow * PITCH + lcol) * 2;   // byte offset within stage

    int a_row_ok = (bm + lrow) < M;
    const __half* a_src_row = A + (size_t)(bm + lrow) * K + lcol;
    const __half* b_src_row = Bt + (size_t)(bn + lrow) * K + lcol;

    // ldmatrix lane offsets (bytes)
    uint32_t a_lane = ((warp_m * 64 + (lane & 15)) * PITCH + ((lane >> 4) * 8)) * 2;
    uint32_t b_lane = ((warp_n * 32 + (lane & 7) + (((lane >> 4) & 1) * 8)) * PITCH
                       + (((lane >> 3) & 1) * 8)) * 2;

    // prologue: issue stages 0..STAGES-2
#pragma unroll
    for (int s = 0; s < GEMM_STAGES - 1; s++) {
        int k0 = s * BK;
        uint32_t ad = as_base + s * GEMM_ABUF + st_off;
        uint32_t bd = bs_base + s * GEMM_ABUF + st_off;
        if (a_row_ok) {
            cp_async16(ad,      a_src_row + k0);
            cp_async16(ad + 16, a_src_row + k0 + 8);
        }
        cp_async16(bd,      b_src_row + k0);
        cp_async16(bd + 16, b_src_row + k0 + 8);
        cp_commit();
    }

    for (int t = 0; t < T; t++) {
        cp_wait<GEMM_STAGES - 2>();
        __syncthreads();

        // issue stage t+STAGES-1
        if (t + GEMM_STAGES - 1 < T) {
            int slot = (t + GEMM_STAGES - 1) % GEMM_STAGES;
            int k0 = (t + GEMM_STAGES - 1) * BK;
            uint32_t ad = as_base + slot * GEMM_ABUF + st_off;
            uint32_t bd = bs_base + slot * GEMM_ABUF + st_off;
            if (a_row_ok) {
                cp_async16(ad,      a_src_row + k0);
                cp_async16(ad + 16, a_src_row + k0 + 8);
            }
            cp_async16(bd,      b_src_row + k0);
            cp_async16(bd + 16, b_src_row + k0 + 8);
        }
        cp_commit();

        int cur = t % GEMM_STAGES;
        uint32_t abase = as_base + cur * GEMM_ABUF + a_lane;
        uint32_t bbase = bs_base + cur * GEMM_ABUF + b_lane;

#pragma unroll
        for (int ks = 0; ks < BK; ks += 16) {
            uint32_t af[4][4], bf[4][2];
#pragma unroll
            for (int mi = 0; mi < 4; mi++)
                ldsm_x4(af[mi], abase + (mi * 16 * PITCH + ks) * 2);
#pragma unroll
            for (int np = 0; np < 2; np++) {
                uint32_t r[4];
                ldsm_x4(r, bbase + (np * 16 * PITCH + ks) * 2);
                bf[np * 2][0] = r[0]; bf[np * 2][1] = r[1];
                bf[np * 2 + 1][0] = r[2]; bf[np * 2 + 1][1] = r[3];
            }
#pragma unroll
            for (int mi = 0; mi < 4; mi++)
#pragma unroll
                for (int ni = 0; ni < 4; ni++)
                    mma_f16(acc[mi][ni], af[mi], bf[ni]);
        }
        __syncthreads();
    }

    // epilogue: fp16 store
    int col_in_frag = (lane & 3) * 2;
#pragma unroll
    for (int mi = 0; mi < 4; mi++) {
#pragma unroll
        for (int ni = 0; ni < 4; ni++) {
            int r0 = bm + warp_m * 64 + mi * 16 + (lane >> 2);
            int c0 = bn + warp_n * 32 + ni * 8 + col_in_frag;
            if (r0 < M) {
                __half2 h = __floats2half2_rn(acc[mi][ni][0], acc[mi][ni][1]);
                *(__half2*)(C16 + (size_t)r0 * N + c0) = h;
            }
            if (r0 + 8 < M) {
                __half2 h = __floats2half2_rn(acc[mi][ni][2], acc[mi][ni][3]);
                *(__half2*)(C16 + (size_t)(r0 + 8) * N + c0) = h;
            }
        }
    }
}

// ---------------------------------------------------------------------------
// Fused aggregation (fp16 gather, precomputed edge norms)
// ---------------------------------------------------------------------------
__global__ void __launch_bounds__(128)
fused_agg_kernel(const __half* __restrict__ h16, const int* __restrict__ cnt,
                 const int2* __restrict__ ell2, const float* __restrict__ bias,
                 __half* __restrict__ out16, float* __restrict__ out32,
                 int write16, int write32) {
    int grp  = threadIdx.x >> 6;          // 0..1
    int lane = threadIdx.x & 63;          // owns halves [lane*8, lane*8+8)
    int d = blockIdx.x * 2 + grp;

    int cd = cnt[d];
    float dd = rsqrtf((float)(cd + 1));
    int deg = min(cd, ELLW);
    const int2* erow = ell2 + (size_t)d * ELLW;

    float4 sp = ((const float4*)(h16 + (size_t)d * FDIM))[lane];
    const __half2* sh = (const __half2*)&sp;
    float sdd = dd * dd;
    float2 s0 = __half22float2(sh[0]);
    float2 s1 = __half22float2(sh[1]);
    float2 s2 = __half22float2(sh[2]);
    float2 s3 = __half22float2(sh[3]);
    float acc[8] = { s0.x * sdd, s0.y * sdd, s1.x * sdd, s1.y * sdd,
                     s2.x * sdd, s2.y * sdd, s3.x * sdd, s3.y * sdd };

#pragma unroll 2
    for (int j = 0; j < deg; j++) {
        int2 e = erow[j];                       // 8B broadcast: (src, nrm)
        int s = e.x;
        float nrm = __int_as_float(e.y);
        float4 p = ((const float4*)(h16 + (size_t)s * FDIM))[lane];
        const __half2* hp = (const __half2*)&p;
        float2 f0 = __half22float2(hp[0]);
        float2 f1 = __half22float2(hp[1]);
        float2 f2 = __half22float2(hp[2]);
        float2 f3 = __half22float2(hp[3]);
        acc[0] += f0.x * nrm; acc[1] += f0.y * nrm;
        acc[2] += f1.x * nrm; acc[3] += f1.y * nrm;
        acc[4] += f2.x * nrm; acc[5] += f2.y * nrm;
        acc[6] += f3.x * nrm; acc[7] += f3.y * nrm;
    }

    const float4* brow = (const float4*)bias;
    float4 b0 = brow[lane * 2];
    float4 b1 = brow[lane * 2 + 1];
    float v[8];
    v[0] = fmaxf(acc[0] + b0.x, 0.f); v[1] = fmaxf(acc[1] + b0.y, 0.f);
    v[2] = fmaxf(acc[2] + b0.z, 0.f); v[3] = fmaxf(acc[3] + b0.w, 0.f);
    v[4] = fmaxf(acc[4] + b1.x, 0.f); v[5] = fmaxf(acc[5] + b1.y, 0.f);
    v[6] = fmaxf(acc[6] + b1.z, 0.f); v[7] = fmaxf(acc[7] + b1.w, 0.f);

    if (write16) {
        __half2 h0 = __floats2half2_rn(v[0], v[1]);
        __half2 h1 = __floats2half2_rn(v[2], v[3]);
        __half2 h2 = __floats2half2_rn(v[4], v[5]);
        __half2 h3 = __floats2half2_rn(v[6], v[7]);
        uint4 u;
        u.x = *(uint32_t*)&h0; u.y = *(uint32_t*)&h1;
        u.z = *(uint32_t*)&h2; u.w = *(uint32_t*)&h3;
        ((uint4*)(out16 + (size_t)d * FDIM))[lane] = u;
    }
    if (write32) {
        float4* orow = (float4*)(out32 + (size_t)d * FDIM);
        orow[lane * 2]     = make_float4(v[0], v[1], v[2], v[3]);
        orow[lane * 2 + 1] = make_float4(v[4], v[5], v[6], v[7]);
    }
}

// ---------------------------------------------------------------------------
// Pooling (batch sorted): grid (graph, 4 strips), binary-search node range
// ---------------------------------------------------------------------------
__global__ void __launch_bounds__(128)
pool_kernel(const float* __restrict__ h, const int* __restrict__ batch,
            float* __restrict__ pooled) {
    int g = blockIdx.x;
    int f = blockIdx.y * 128 + threadIdx.x;

    int lo = 0, hi = NNODES;
    while (lo < hi) { int mid = (lo + hi) >> 1; if (batch[mid] < g) lo = mid + 1; else hi = mid; }
    int beg = lo;
    hi = NNODES;
    while (lo < hi) { int mid = (lo + hi) >> 1; if (batch[mid] < g + 1) lo = mid + 1; else hi = mid; }
    int end = lo;

    float acc = 0.f;
    for (int n = beg; n < end; n++)
        acc += h[(size_t)n * FDIM + f];
    pooled[g * FDIM + f] = acc;
}

// ---------------------------------------------------------------------------
// Final small GEMM: out[64,128] = pooled[64,512] @ Wlin[512,128] + blin
// ---------------------------------------------------------------------------
__global__ void __launch_bounds__(128)
final_gemm_kernel(const float* __restrict__ pooled,
                  const float* __restrict__ Wlin,
                  const float* __restrict__ blin,
                  float* __restrict__ out) {
    __shared__ float p[FDIM];
    int g = blockIdx.x;
    int o = threadIdx.x;   // 128
    for (int k = o; k < FDIM; k += ODIM) p[k] = pooled[g * FDIM + k];
    __syncthreads();
    float acc = blin[o];
#pragma unroll 8
    for (int k = 0; k < FDIM; k++) acc += p[k] * Wlin[k * ODIM + o];
    out[g * ODIM + o] = acc;
}

// ---------------------------------------------------------------------------
// Launch
// ---------------------------------------------------------------------------
extern "C" void kernel_launch(void* const* d_in, const int* in_sizes, int n_in,
                              void* d_out, int out_size) {
    const float* x    = (const float*)d_in[0];
    const float* W1   = (const float*)d_in[1];
    const float* b1   = (const float*)d_in[2];
    const float* W2   = (const float*)d_in[3];
    const float* b2   = (const float*)d_in[4];
    const float* Wlin = (const float*)d_in[5];
    const float* blin = (const float*)d_in[6];
    const int* edge_index = (const int*)d_in[7];   // harness maps int64 -> int32
    const int* batch      = (const int*)d_in[8];

    const int* src = edge_index;
    const int* dst = edge_index + NEDGES;

    __half *x16, *w1t, *w2t, *a16, *b16;
    float *buf2, *pooled_scratch;
    int *cnt;
    int2 *ell2;
    cudaGetSymbolAddress((void**)&x16, g_x16);
    cudaGetSymbolAddress((void**)&w1t, g_w1t);
    cudaGetSymbolAddress((void**)&w2t, g_w2t);
    cudaGetSymbolAddress((void**)&a16, g_a16);
    cudaGetSymbolAddress((void**)&b16, g_b16);
    cudaGetSymbolAddress((void**)&buf2, g_buf2);
    cudaGetSymbolAddress((void**)&pooled_scratch, g_pooled);
    cudaGetSymbolAddress((void**)&cnt, g_cnt);
    cudaGetSymbolAddress((void**)&ell2, g_ell2);

    float* pooled;
    float* out2;
    if (out_size >= NGRAPH * FDIM + NGRAPH * ODIM) {
        pooled = (float*)d_out;
        out2   = (float*)d_out + NGRAPH * FDIM;
    } else {
        pooled = pooled_scratch;
        out2   = (float*)d_out;
    }

    // One-time setup: side stream + dynamic smem attribute.
    static cudaStream_t side = nullptr;
    static cudaEvent_t evFork = nullptr, evJoin = nullptr;
    static bool inited = false;
    if (!inited) {
        inited = true;
        cudaFuncSetAttribute(h16_gemm_kernel,
                             cudaFuncAttributeMaxDynamicSharedMemorySize, GEMM_SMEM);
        if (cudaStreamCreateWithFlags(&side, cudaStreamNonBlocking) != cudaSuccess)
            side = nullptr;
        if (side) {
            if (cudaEventCreateWithFlags(&evFork, cudaEventDisableTiming) != cudaSuccess ||
                cudaEventCreateWithFlags(&evJoin, cudaEventDisableTiming) != cudaSuccess)
                side = nullptr;
        }
    }

    dim3 gemm_grid(FDIM / 128, (NNODES + 127) / 128);

    // 1. convert + transpose + zero cnt (single launch)
    convert_zero_kernel<<<CONVERT_GRID, 256>>>(x, W1, W2, x16, w1t, w2t, cnt);

    if (side) {
        cudaEventRecord(evFork, 0);
        cudaStreamWaitEvent(side, evFork, 0);
        scatter_ell_kernel<<<(NEDGES + 255) / 256, 256, 0, side>>>(src, dst, cnt, ell2, NEDGES);
        nrm_kernel<<<(NNODES * ELLW + 255) / 256, 256, 0, side>>>(cnt, ell2);
        cudaEventRecord(evJoin, side);
        h16_gemm_kernel<<<gemm_grid, 256, GEMM_SMEM>>>(x16, w1t, a16, NNODES);
        cudaStreamWaitEvent(0, evJoin, 0);
    } else {
        scatter_ell_kernel<<<(NEDGES + 255) / 256, 256>>>(src, dst, cnt, ell2, NEDGES);
        nrm_kernel<<<(NNODES * ELLW + 255) / 256, 256>>>(cnt, ell2);
        h16_gemm_kernel<<<gemm_grid, 256, GEMM_SMEM>>>(x16, w1t, a16, NNODES);
    }

    // agg1
    fused_agg_kernel<<<NNODES / 2, 128>>>(a16, cnt, ell2, b1, b16, nullptr, 1, 0);

    // Layer 2
    h16_gemm_kernel<<<gemm_grid, 256, GEMM_SMEM>>>(b16, w2t, a16, NNODES);
    fused_agg_kernel<<<NNODES / 2, 128>>>(a16, cnt, ell2, b2, nullptr, buf2, 0, 1);

    // Pool + final linear
    {
        dim3 pg(NGRAPH, FDIM / 128);
        pool_kernel<<<pg, 128>>>(buf2, batch, pooled);
    }
    final_gemm_kernel<<<NGRAPH, ODIM>>>(pooled, Wlin, blin, out2);
}

// round 16
// speedup vs baseline: 1.1452x; 1.0789x over previous
#include <cuda_runtime.h>
#include <cuda_fp16.h>
#include <cstdint>

#define NNODES 10000
#define NEDGES 160000
#define FDIM   512
#define NGRAPH 64
#define ODIM   128
#define ELLW   64

// Scratch (device globals; no allocation allowed)
__device__ __half g_x16[NNODES * FDIM];     // fp16 input features
__device__ __half g_w1t[FDIM * FDIM];       // W1 transposed [N][K] fp16
__device__ __half g_w2t[FDIM * FDIM];       // W2 transposed [N][K] fp16
__device__ __half g_a16[NNODES * FDIM];     // gemm output (pre-agg)
__device__ __half g_b16[NNODES * FDIM];     // agg1 output (layer-2 input)
__device__ float  g_buf2[NNODES * FDIM];    // agg2 fp32 output (for pool)
__device__ int    g_cnt[NNODES];
__device__ int2   g_ell2[NNODES * ELLW];    // (src, nrm bits)
__device__ float  g_pooled[NGRAPH * FDIM];

__device__ __forceinline__ int clampi(int v, int lo, int hi) {
    return v < lo ? lo : (v > hi ? hi : v);
}

__device__ __forceinline__ void mma_f16(float* c, const uint32_t* a, const uint32_t* b) {
    asm volatile(
        "mma.sync.aligned.m16n8k16.row.col.f32.f16.f16.f32 "
        "{%0,%1,%2,%3}, {%4,%5,%6,%7}, {%8,%9}, {%0,%1,%2,%3};"
        : "+f"(c[0]), "+f"(c[1]), "+f"(c[2]), "+f"(c[3])
        : "r"(a[0]), "r"(a[1]), "r"(a[2]), "r"(a[3]), "r"(b[0]), "r"(b[1]));
}

__device__ __forceinline__ void ldsm_x4(uint32_t* r, uint32_t addr) {
    asm volatile(
        "ldmatrix.sync.aligned.m8n8.x4.shared.b16 {%0,%1,%2,%3}, [%4];"
        : "=r"(r[0]), "=r"(r[1]), "=r"(r[2]), "=r"(r[3]) : "r"(addr));
}

__device__ __forceinline__ void cp_async16(uint32_t smem_dst, const void* gmem_src) {
    asm volatile("cp.async.cg.shared.global [%0], [%1], 16;\n"
                 :: "r"(smem_dst), "l"(gmem_src) : "memory");
}
__device__ __forceinline__ void cp_commit() {
    asm volatile("cp.async.commit_group;\n" ::: "memory");
}
template <int N>
__device__ __forceinline__ void cp_wait() {
    asm volatile("cp.async.wait_group %0;\n" :: "n"(N) : "memory");
}

// ---------------------------------------------------------------------------
// Fused convert + cnt-zero, block-range dispatch
// ---------------------------------------------------------------------------
#define XBLK   (NNODES * FDIM / 4 / 256)        // 5000
#define WTILES (FDIM / 32 * FDIM / 32)          // 256 per weight
#define CBLK   ((NNODES + 255) / 256)           // 40
#define CONVERT_GRID (XBLK + 2 * WTILES + CBLK)

__global__ void convert_zero_kernel(const float* __restrict__ x,
                                    const float* __restrict__ W1,
                                    const float* __restrict__ W2,
                                    __half* __restrict__ x16,
                                    __half* __restrict__ w1t,
                                    __half* __restrict__ w2t,
                                    int* __restrict__ cnt) {
    int b = blockIdx.x;
    int tid = threadIdx.x;
    if (b < XBLK) {
        int i = b * 256 + tid;
        float4 v = ((const float4*)x)[i];
        __half2 h0 = __floats2half2_rn(v.x, v.y);
        __half2 h1 = __floats2half2_rn(v.z, v.w);
        uint2 u;
        u.x = *(uint32_t*)&h0; u.y = *(uint32_t*)&h1;
        ((uint2*)x16)[i] = u;
    } else if (b < XBLK + 2 * WTILES) {
        __shared__ float tile[32][33];
        int wi = b - XBLK;
        const float* W = (wi < WTILES) ? W1 : W2;
        __half* Wt = (wi < WTILES) ? w1t : w2t;
        int t = wi & (WTILES - 1);
        int k0 = (t >> 4) * 32;
        int n0 = (t & 15) * 32;
        int tx = tid & 31;
        int ty = tid >> 5;          // 0..7
#pragma unroll
        for (int i = ty; i < 32; i += 8)
            tile[i][tx] = W[(size_t)(k0 + i) * FDIM + n0 + tx];
        __syncthreads();
#pragma unroll
        for (int i = ty; i < 32; i += 8)
            Wt[(size_t)(n0 + i) * FDIM + k0 + tx] = __float2half_rn(tile[tx][i]);
    } else {
        int i = (b - XBLK - 2 * WTILES) * 256 + tid;
        if (i < NNODES) cnt[i] = 0;
    }
}

// ---------------------------------------------------------------------------
// ELL scatter (fills .x = src), then nrm pass (fills .y after cnt final)
// ---------------------------------------------------------------------------
__global__ void scatter_ell_kernel(const int* __restrict__ src, const int* __restrict__ dst,
                                   int* cnt, int2* ell2, int e) {
    int i = blockIdx.x * blockDim.x + threadIdx.x;
    if (i >= e) return;
    int d = clampi(dst[i], 0, NNODES - 1);
    int s = clampi(src[i], 0, NNODES - 1);
    int slot = atomicAdd(&cnt[d], 1);
    if (slot < ELLW) ell2[d * ELLW + slot].x = s;
}

__global__ void nrm_kernel(const int* __restrict__ cnt, int2* __restrict__ ell2) {
    int i = blockIdx.x * blockDim.x + threadIdx.x;
    if (i >= NNODES * ELLW) return;
    int d = i >> 6;
    int slot = i & (ELLW - 1);
    int cd = cnt[d];
    if (slot >= min(cd, ELLW)) return;
    int s = ell2[i].x;
    float nrm = rsqrtf((float)(cnt[s] + 1)) * rsqrtf((float)(cd + 1));
    ell2[i].y = __float_as_int(nrm);
}

// ---------------------------------------------------------------------------
// fp16 tensor-core GEMM: 4-stage cp.async pipeline + ldmatrix, 512 threads.
// C16[M,512] = A16[M,512] @ Bt16[512,512]^T, fp32 accum.
// 128x128 tile, BK=32, 16 warps (4x4), warp tile 32x32, m16n8k16.
// Dynamic smem: 4 stages x (A 10240B + B 10240B) = 81920B.
// ---------------------------------------------------------------------------
#define GEMM_BK     32
#define GEMM_PITCH  40                          // halves per row (80B)
#define GEMM_ABUF   (128 * GEMM_PITCH * 2)      // bytes per stage per operand
#define GEMM_STAGES 4
#define GEMM_SMEM   (2 * GEMM_STAGES * GEMM_ABUF)   // 81920

__global__ void __launch_bounds__(512, 2)
h16_gemm_kernel(const __half* __restrict__ A, const __half* __restrict__ Bt,
                __half* __restrict__ C16, int M) {
    const int K = FDIM, N = FDIM, BK = GEMM_BK;
    const int PITCH = GEMM_PITCH;
    extern __shared__ __half smem[];

    int tid = threadIdx.x;
    int lane = tid & 31;
    int wid = tid >> 5;          // 0..15
    int warp_m = wid >> 2;       // 0..3
    int warp_n = wid & 3;        // 0..3

    int bm = blockIdx.y * 128;
    int bn = blockIdx.x * 128;

    int lrow = tid >> 2;         // 0..127
    int lcol = (tid & 3) * 8;    // halves: 0,8,16,24

    float acc[2][4][4] = {};

    const int T = K / BK;        // 16

    uint32_t as_base = (uint32_t)__cvta_generic_to_shared(smem);
    uint32_t bs_base = as_base + GEMM_STAGES * GEMM_ABUF;
    uint32_t st_off = (lrow * PITCH + lcol) * 2;   // byte offset within stage

    int a_row_ok = (bm + lrow) < M;
    const __half* a_src_row = A + (size_t)(bm + lrow) * K + lcol;
    const __half* b_src_row = Bt + (size_t)(bn + lrow) * K + lcol;

    // ldmatrix lane offsets (bytes)
    uint32_t a_lane = ((warp_m * 32 + (lane & 15)) * PITCH + ((lane >> 4) * 8)) * 2;
    uint32_t b_lane = ((warp_n * 32 + (lane & 7) + (((lane >> 4) & 1) * 8)) * PITCH
                       + (((lane >> 3) & 1) * 8)) * 2;

    // prologue: issue stages 0..STAGES-2
#pragma unroll
    for (int s = 0; s < GEMM_STAGES - 1; s++) {
        int k0 = s * BK;
        uint32_t ad = as_base + s * GEMM_ABUF + st_off;
        uint32_t bd = bs_base + s * GEMM_ABUF + st_off;
        if (a_row_ok) cp_async16(ad, a_src_row + k0);
        cp_async16(bd, b_src_row + k0);
        cp_commit();
    }

    for (int t = 0; t < T; t++) {
        cp_wait<GEMM_STAGES - 2>();
        __syncthreads();

        // issue stage t+STAGES-1
        if (t + GEMM_STAGES - 1 < T) {
            int slot = (t + GEMM_STAGES - 1) % GEMM_STAGES;
            int k0 = (t + GEMM_STAGES - 1) * BK;
            uint32_t ad = as_base + slot * GEMM_ABUF + st_off;
            uint32_t bd = bs_base + slot * GEMM_ABUF + st_off;
            if (a_row_ok) cp_async16(ad, a_src_row + k0);
            cp_async16(bd, b_src_row + k0);
        }
        cp_commit();

        int cur = t % GEMM_STAGES;
        uint32_t abase = as_base + cur * GEMM_ABUF + a_lane;
        uint32_t bbase = bs_base + cur * GEMM_ABUF + b_lane;

#pragma unroll
        for (int ks = 0; ks < BK; ks += 16) {
            uint32_t af[2][4], bf[4][2];
#pragma unroll
            for (int mi = 0; mi < 2; mi++)
                ldsm_x4(af[mi], abase + (mi * 16 * PITCH + ks) * 2);
#pragma unroll
            for (int np = 0; np < 2; np++) {
                uint32_t r[4];
                ldsm_x4(r, bbase + (np * 16 * PITCH + ks) * 2);
                bf[np * 2][0] = r[0]; bf[np * 2][1] = r[1];
                bf[np * 2 + 1][0] = r[2]; bf[np * 2 + 1][1] = r[3];
            }
#pragma unroll
            for (int mi = 0; mi < 2; mi++)
#pragma unroll
                for (int ni = 0; ni < 4; ni++)
                    mma_f16(acc[mi][ni], af[mi], bf[ni]);
        }
        __syncthreads();
    }

    // epilogue: fp16 store
    int col_in_frag = (lane & 3) * 2;
#pragma unroll
    for (int mi = 0; mi < 2; mi++) {
#pragma unroll
        for (int ni = 0; ni < 4; ni++) {
            int r0 = bm + warp_m * 32 + mi * 16 + (lane >> 2);
            int c0 = bn + warp_n * 32 + ni * 8 + col_in_frag;
            if (r0 < M) {
                __half2 h = __floats2half2_rn(acc[mi][ni][0], acc[mi][ni][1]);
                *(__half2*)(C16 + (size_t)r0 * N + c0) = h;
            }
            if (r0 + 8 < M) {
                __half2 h = __floats2half2_rn(acc[mi][ni][2], acc[mi][ni][3]);
                *(__half2*)(C16 + (size_t)(r0 + 8) * N + c0) = h;
            }
        }
    }
}

// ---------------------------------------------------------------------------
// Fused aggregation (fp16 gather, precomputed edge norms)
// ---------------------------------------------------------------------------
__global__ void __launch_bounds__(128)
fused_agg_kernel(const __half* __restrict__ h16, const int* __restrict__ cnt,
                 const int2* __restrict__ ell2, const float* __restrict__ bias,
                 __half* __restrict__ out16, float* __restrict__ out32,
                 int write16, int write32) {
    int grp  = threadIdx.x >> 6;          // 0..1
    int lane = threadIdx.x & 63;          // owns halves [lane*8, lane*8+8)
    int d = blockIdx.x * 2 + grp;

    int cd = cnt[d];
    float dd = rsqrtf((float)(cd + 1));
    int deg = min(cd, ELLW);
    const int2* erow = ell2 + (size_t)d * ELLW;

    float4 sp = ((const float4*)(h16 + (size_t)d * FDIM))[lane];
    const __half2* sh = (const __half2*)&sp;
    float sdd = dd * dd;
    float2 s0 = __half22float2(sh[0]);
    float2 s1 = __half22float2(sh[1]);
    float2 s2 = __half22float2(sh[2]);
    float2 s3 = __half22float2(sh[3]);
    float acc[8] = { s0.x * sdd, s0.y * sdd, s1.x * sdd, s1.y * sdd,
                     s2.x * sdd, s2.y * sdd, s3.x * sdd, s3.y * sdd };

#pragma unroll 2
    for (int j = 0; j < deg; j++) {
        int2 e = erow[j];                       // 8B broadcast: (src, nrm)
        int s = e.x;
        float nrm = __int_as_float(e.y);
        float4 p = ((const float4*)(h16 + (size_t)s * FDIM))[lane];
        const __half2* hp = (const __half2*)&p;
        float2 f0 = __half22float2(hp[0]);
        float2 f1 = __half22float2(hp[1]);
        float2 f2 = __half22float2(hp[2]);
        float2 f3 = __half22float2(hp[3]);
        acc[0] += f0.x * nrm; acc[1] += f0.y * nrm;
        acc[2] += f1.x * nrm; acc[3] += f1.y * nrm;
        acc[4] += f2.x * nrm; acc[5] += f2.y * nrm;
        acc[6] += f3.x * nrm; acc[7] += f3.y * nrm;
    }

    const float4* brow = (const float4*)bias;
    float4 b0 = brow[lane * 2];
    float4 b1 = brow[lane * 2 + 1];
    float v[8];
    v[0] = fmaxf(acc[0] + b0.x, 0.f); v[1] = fmaxf(acc[1] + b0.y, 0.f);
    v[2] = fmaxf(acc[2] + b0.z, 0.f); v[3] = fmaxf(acc[3] + b0.w, 0.f);
    v[4] = fmaxf(acc[4] + b1.x, 0.f); v[5] = fmaxf(acc[5] + b1.y, 0.f);
    v[6] = fmaxf(acc[6] + b1.z, 0.f); v[7] = fmaxf(acc[7] + b1.w, 0.f);

    if (write16) {
        __half2 h0 = __floats2half2_rn(v[0], v[1]);
        __half2 h1 = __floats2half2_rn(v[2], v[3]);
        __half2 h2 = __floats2half2_rn(v[4], v[5]);
        __half2 h3 = __floats2half2_rn(v[6], v[7]);
        uint4 u;
        u.x = *(uint32_t*)&h0; u.y = *(uint32_t*)&h1;
        u.z = *(uint32_t*)&h2; u.w = *(uint32_t*)&h3;
        ((uint4*)(out16 + (size_t)d * FDIM))[lane] = u;
    }
    if (write32) {
        float4* orow = (float4*)(out32 + (size_t)d * FDIM);
        orow[lane * 2]     = make_float4(v[0], v[1], v[2], v[3]);
        orow[lane * 2 + 1] = make_float4(v[4], v[5], v[6], v[7]);
    }
}

// ---------------------------------------------------------------------------
// Pooling (batch sorted): grid (graph, 4 strips), binary-search node range
// ---------------------------------------------------------------------------
__global__ void __launch_bounds__(128)
pool_kernel(const float* __restrict__ h, const int* __restrict__ batch,
            float* __restrict__ pooled) {
    int g = blockIdx.x;
    int f = blockIdx.y * 128 + threadIdx.x;

    int lo = 0, hi = NNODES;
    while (lo < hi) { int mid = (lo + hi) >> 1; if (batch[mid] < g) lo = mid + 1; else hi = mid; }
    int beg = lo;
    hi = NNODES;
    while (lo < hi) { int mid = (lo + hi) >> 1; if (batch[mid] < g + 1) lo = mid + 1; else hi = mid; }
    int end = lo;

    float acc = 0.f;
    for (int n = beg; n < end; n++)
        acc += h[(size_t)n * FDIM + f];
    pooled[g * FDIM + f] = acc;
}

// ---------------------------------------------------------------------------
// Final small GEMM: out[64,128] = pooled[64,512] @ Wlin[512,128] + blin
// ---------------------------------------------------------------------------
__global__ void __launch_bounds__(128)
final_gemm_kernel(const float* __restrict__ pooled,
                  const float* __restrict__ Wlin,
                  const float* __restrict__ blin,
                  float* __restrict__ out) {
    __shared__ float p[FDIM];
    int g = blockIdx.x;
    int o = threadIdx.x;   // 128
    for (int k = o; k < FDIM; k += ODIM) p[k] = pooled[g * FDIM + k];
    __syncthreads();
    float acc = blin[o];
#pragma unroll 8
    for (int k = 0; k < FDIM; k++) acc += p[k] * Wlin[k * ODIM + o];
    out[g * ODIM + o] = acc;
}

// ---------------------------------------------------------------------------
// Launch
// ---------------------------------------------------------------------------
extern "C" void kernel_launch(void* const* d_in, const int* in_sizes, int n_in,
                              void* d_out, int out_size) {
    const float* x    = (const float*)d_in[0];
    const float* W1   = (const float*)d_in[1];
    const float* b1   = (const float*)d_in[2];
    const float* W2   = (const float*)d_in[3];
    const float* b2   = (const float*)d_in[4];
    const float* Wlin = (const float*)d_in[5];
    const float* blin = (const float*)d_in[6];
    const int* edge_index = (const int*)d_in[7];   // harness maps int64 -> int32
    const int* batch      = (const int*)d_in[8];

    const int* src = edge_index;
    const int* dst = edge_index + NEDGES;

    __half *x16, *w1t, *w2t, *a16, *b16;
    float *buf2, *pooled_scratch;
    int *cnt;
    int2 *ell2;
    cudaGetSymbolAddress((void**)&x16, g_x16);
    cudaGetSymbolAddress((void**)&w1t, g_w1t);
    cudaGetSymbolAddress((void**)&w2t, g_w2t);
    cudaGetSymbolAddress((void**)&a16, g_a16);
    cudaGetSymbolAddress((void**)&b16, g_b16);
    cudaGetSymbolAddress((void**)&buf2, g_buf2);
    cudaGetSymbolAddress((void**)&pooled_scratch, g_pooled);
    cudaGetSymbolAddress((void**)&cnt, g_cnt);
    cudaGetSymbolAddress((void**)&ell2, g_ell2);

    float* pooled;
    float* out2;
    if (out_size >= NGRAPH * FDIM + NGRAPH * ODIM) {
        pooled = (float*)d_out;
        out2   = (float*)d_out + NGRAPH * FDIM;
    } else {
        pooled = pooled_scratch;
        out2   = (float*)d_out;
    }

    // One-time setup: side stream + dynamic smem attribute.
    static cudaStream_t side = nullptr;
    static cudaEvent_t evFork = nullptr, evJoin = nullptr;
    static bool inited = false;
    if (!inited) {
        inited = true;
        cudaFuncSetAttribute(h16_gemm_kernel,
                             cudaFuncAttributeMaxDynamicSharedMemorySize, GEMM_SMEM);
        if (cudaStreamCreateWithFlags(&side, cudaStreamNonBlocking) != cudaSuccess)
            side = nullptr;
        if (side) {
            if (cudaEventCreateWithFlags(&evFork, cudaEventDisableTiming) != cudaSuccess ||
                cudaEventCreateWithFlags(&evJoin, cudaEventDisableTiming) != cudaSuccess)
                side = nullptr;
        }
    }

    dim3 gemm_grid(FDIM / 128, (NNODES + 127) / 128);

    // 1. convert + transpose + zero cnt (single launch)
    convert_zero_kernel<<<CONVERT_GRID, 256>>>(x, W1, W2, x16, w1t, w2t, cnt);

    if (side) {
        cudaEventRecord(evFork, 0);
        cudaStreamWaitEvent(side, evFork, 0);
        scatter_ell_kernel<<<(NEDGES + 255) / 256, 256, 0, side>>>(src, dst, cnt, ell2, NEDGES);
        nrm_kernel<<<(NNODES * ELLW + 255) / 256, 256, 0, side>>>(cnt, ell2);
        cudaEventRecord(evJoin, side);
        h16_gemm_kernel<<<gemm_grid, 512, GEMM_SMEM>>>(x16, w1t, a16, NNODES);
        cudaStreamWaitEvent(0, evJoin, 0);
    } else {
        scatter_ell_kernel<<<(NEDGES + 255) / 256, 256>>>(src, dst, cnt, ell2, NEDGES);
        nrm_kernel<<<(NNODES * ELLW + 255) / 256, 256>>>(cnt, ell2);
        h16_gemm_kernel<<<gemm_grid, 512, GEMM_SMEM>>>(x16, w1t, a16, NNODES);
    }

    // agg1
    fused_agg_kernel<<<NNODES / 2, 128>>>(a16, cnt, ell2, b1, b16, nullptr, 1, 0);

    // Layer 2
    h16_gemm_kernel<<<gemm_grid, 512, GEMM_SMEM>>>(b16, w2t, a16, NNODES);
    fused_agg_kernel<<<NNODES / 2, 128>>>(a16, cnt, ell2, b2, nullptr, buf2, 0, 1);

    // Pool + final linear
    {
        dim3 pg(NGRAPH, FDIM / 128);
        pool_kernel<<<pg, 128>>>(buf2, batch, pooled);
    }
    final_gemm_kernel<<<NGRAPH, ODIM>>>(pooled, Wlin, blin, out2);
}

// round 17
// speedup vs baseline: 1.2752x; 1.1135x over previous
#include <cuda_runtime.h>
#include <cuda_fp16.h>
#include <cstdint>

#define NNODES 10000
#define NEDGES 160000
#define FDIM   512
#define NGRAPH 64
#define ODIM   128
#define ELLW   64

// Scratch (device globals; no allocation allowed)
__device__ __half g_x16[NNODES * FDIM];     // fp16 input features
__device__ __half g_w1t[FDIM * FDIM];       // W1 transposed [N][K] fp16
__device__ __half g_w2t[FDIM * FDIM];       // W2 transposed [N][K] fp16
__device__ __half g_a16[NNODES * FDIM];     // gemm output (pre-agg)
__device__ __half g_b16[NNODES * FDIM];     // agg output (layer-2 input / pool input)
__device__ int    g_cnt[NNODES];
__device__ int2   g_ell2[NNODES * ELLW];    // (src, nrm bits)
__device__ float  g_pooled[NGRAPH * FDIM];

__device__ __forceinline__ int clampi(int v, int lo, int hi) {
    return v < lo ? lo : (v > hi ? hi : v);
}

__device__ __forceinline__ void mma_f16(float* c, const uint32_t* a, const uint32_t* b) {
    asm volatile(
        "mma.sync.aligned.m16n8k16.row.col.f32.f16.f16.f32 "
        "{%0,%1,%2,%3}, {%4,%5,%6,%7}, {%8,%9}, {%0,%1,%2,%3};"
        : "+f"(c[0]), "+f"(c[1]), "+f"(c[2]), "+f"(c[3])
        : "r"(a[0]), "r"(a[1]), "r"(a[2]), "r"(a[3]), "r"(b[0]), "r"(b[1]));
}

__device__ __forceinline__ void ldsm_x4(uint32_t* r, uint32_t addr) {
    asm volatile(
        "ldmatrix.sync.aligned.m8n8.x4.shared.b16 {%0,%1,%2,%3}, [%4];"
        : "=r"(r[0]), "=r"(r[1]), "=r"(r[2]), "=r"(r[3]) : "r"(addr));
}

__device__ __forceinline__ void cp_async16(uint32_t smem_dst, const void* gmem_src) {
    asm volatile("cp.async.cg.shared.global [%0], [%1], 16;\n"
                 :: "r"(smem_dst), "l"(gmem_src) : "memory");
}
__device__ __forceinline__ void cp_commit() {
    asm volatile("cp.async.commit_group;\n" ::: "memory");
}
template <int N>
__device__ __forceinline__ void cp_wait() {
    asm volatile("cp.async.wait_group %0;\n" :: "n"(N) : "memory");
}

// ---------------------------------------------------------------------------
// Fused convert + cnt-zero, block-range dispatch
// ---------------------------------------------------------------------------
#define XBLK   (NNODES * FDIM / 4 / 256)        // 5000
#define WTILES (FDIM / 32 * FDIM / 32)          // 256 per weight
#define CBLK   ((NNODES + 255) / 256)           // 40
#define CONVERT_GRID (XBLK + 2 * WTILES + CBLK)

__global__ void convert_zero_kernel(const float* __restrict__ x,
                                    const float* __restrict__ W1,
                                    const float* __restrict__ W2,
                                    __half* __restrict__ x16,
                                    __half* __restrict__ w1t,
                                    __half* __restrict__ w2t,
                                    int* __restrict__ cnt) {
    int b = blockIdx.x;
    int tid = threadIdx.x;
    if (b < XBLK) {
        int i = b * 256 + tid;
        float4 v = ((const float4*)x)[i];
        __half2 h0 = __floats2half2_rn(v.x, v.y);
        __half2 h1 = __floats2half2_rn(v.z, v.w);
        uint2 u;
        u.x = *(uint32_t*)&h0; u.y = *(uint32_t*)&h1;
        ((uint2*)x16)[i] = u;
    } else if (b < XBLK + 2 * WTILES) {
        __shared__ float tile[32][33];
        int wi = b - XBLK;
        const float* W = (wi < WTILES) ? W1 : W2;
        __half* Wt = (wi < WTILES) ? w1t : w2t;
        int t = wi & (WTILES - 1);
        int k0 = (t >> 4) * 32;
        int n0 = (t & 15) * 32;
        int tx = tid & 31;
        int ty = tid >> 5;          // 0..7
#pragma unroll
        for (int i = ty; i < 32; i += 8)
            tile[i][tx] = W[(size_t)(k0 + i) * FDIM + n0 + tx];
        __syncthreads();
#pragma unroll
        for (int i = ty; i < 32; i += 8)
            Wt[(size_t)(n0 + i) * FDIM + k0 + tx] = __float2half_rn(tile[tx][i]);
    } else {
        int i = (b - XBLK - 2 * WTILES) * 256 + tid;
        if (i < NNODES) cnt[i] = 0;
    }
}

// ---------------------------------------------------------------------------
// ELL scatter (fills .x = src), then nrm pass (fills .y after cnt final)
// ---------------------------------------------------------------------------
__global__ void scatter_ell_kernel(const int* __restrict__ src, const int* __restrict__ dst,
                                   int* cnt, int2* ell2, int e) {
    int i = blockIdx.x * blockDim.x + threadIdx.x;
    if (i >= e) return;
    int d = clampi(dst[i], 0, NNODES - 1);
    int s = clampi(src[i], 0, NNODES - 1);
    int slot = atomicAdd(&cnt[d], 1);
    if (slot < ELLW) ell2[d * ELLW + slot].x = s;
}

__global__ void nrm_kernel(const int* __restrict__ cnt, int2* __restrict__ ell2) {
    int i = blockIdx.x * blockDim.x + threadIdx.x;
    if (i >= NNODES * ELLW) return;
    int d = i >> 6;
    int slot = i & (ELLW - 1);
    int cd = cnt[d];
    if (slot >= min(cd, ELLW)) return;
    int s = ell2[i].x;
    float nrm = rsqrtf((float)(cnt[s] + 1)) * rsqrtf((float)(cd + 1));
    ell2[i].y = __float_as_int(nrm);
}

// ---------------------------------------------------------------------------
// fp16 tensor-core GEMM: 3-stage cp.async pipeline, BK=64, single barrier/iter.
// C16[M,512] = A16[M,512] @ Bt16[512,512]^T, fp32 accum.
// 128x128 tile, 16 warps (4x4), warp tile 32x32, m16n8k16, 512 threads.
// Dynamic smem: 3 stages x (A 18432B + B 18432B) = 110592B.
// ---------------------------------------------------------------------------
#define GEMM_BK     64
#define GEMM_PITCH  72                          // halves per row (144B)
#define GEMM_ABUF   (128 * GEMM_PITCH * 2)      // 18432 bytes per stage per operand
#define GEMM_STAGES 3
#define GEMM_SMEM   (2 * GEMM_STAGES * GEMM_ABUF)   // 110592

__global__ void __launch_bounds__(512, 2)
h16_gemm_kernel(const __half* __restrict__ A, const __half* __restrict__ Bt,
                __half* __restrict__ C16, int M) {
    const int K = FDIM, N = FDIM, BK = GEMM_BK;
    const int PITCH = GEMM_PITCH;
    extern __shared__ __half smem[];

    int tid = threadIdx.x;
    int lane = tid & 31;
    int wid = tid >> 5;          // 0..15
    int warp_m = wid >> 2;       // 0..3
    int warp_n = wid & 3;        // 0..3

    int bm = blockIdx.y * 128;
    int bn = blockIdx.x * 128;

    int lrow = tid >> 2;         // 0..127
    int lcol = (tid & 3) * 16;   // halves: 0,16,32,48

    float acc[2][4][4] = {};

    const int T = K / BK;        // 8

    uint32_t as_base = (uint32_t)__cvta_generic_to_shared(smem);
    uint32_t bs_base = as_base + GEMM_STAGES * GEMM_ABUF;
    uint32_t st_off = (lrow * PITCH + lcol) * 2;   // byte offset within stage

    int a_row_ok = (bm + lrow) < M;
    const __half* a_src_row = A + (size_t)(bm + lrow) * K + lcol;
    const __half* b_src_row = Bt + (size_t)(bn + lrow) * K + lcol;

    // ldmatrix lane offsets (bytes)
    uint32_t a_lane = ((warp_m * 32 + (lane & 15)) * PITCH + ((lane >> 4) * 8)) * 2;
    uint32_t b_lane = ((warp_n * 32 + (lane & 7) + (((lane >> 4) & 1) * 8)) * PITCH
                       + (((lane >> 3) & 1) * 8)) * 2;

    // prologue: issue stages 0,1
#pragma unroll
    for (int s = 0; s < GEMM_STAGES - 1; s++) {
        int k0 = s * BK;
        uint32_t ad = as_base + s * GEMM_ABUF + st_off;
        uint32_t bd = bs_base + s * GEMM_ABUF + st_off;
        if (a_row_ok) {
            cp_async16(ad,      a_src_row + k0);
            cp_async16(ad + 16, a_src_row + k0 + 8);
        }
        cp_async16(bd,      b_src_row + k0);
        cp_async16(bd + 16, b_src_row + k0 + 8);
        cp_commit();
    }

    for (int t = 0; t < T; t++) {
        cp_wait<GEMM_STAGES - 2>();
        __syncthreads();              // single barrier: orders stage-t visibility AND
                                      // protects slot (t%3) from next iteration's writers

        if (t + GEMM_STAGES - 1 < T) {
            int slot = (t + GEMM_STAGES - 1) % GEMM_STAGES;
            int k0 = (t + GEMM_STAGES - 1) * BK;
            uint32_t ad = as_base + slot * GEMM_ABUF + st_off;
            uint32_t bd = bs_base + slot * GEMM_ABUF + st_off;
            if (a_row_ok) {
                cp_async16(ad,      a_src_row + k0);
                cp_async16(ad + 16, a_src_row + k0 + 8);
            }
            cp_async16(bd,      b_src_row + k0);
            cp_async16(bd + 16, b_src_row + k0 + 8);
        }
        cp_commit();

        int cur = t % GEMM_STAGES;
        uint32_t abase = as_base + cur * GEMM_ABUF + a_lane;
        uint32_t bbase = bs_base + cur * GEMM_ABUF + b_lane;

#pragma unroll
        for (int ks = 0; ks < BK; ks += 16) {
            uint32_t af[2][4], bf[4][2];
#pragma unroll
            for (int mi = 0; mi < 2; mi++)
                ldsm_x4(af[mi], abase + (mi * 16 * PITCH + ks) * 2);
#pragma unroll
            for (int np = 0; np < 2; np++) {
                uint32_t r[4];
                ldsm_x4(r, bbase + (np * 16 * PITCH + ks) * 2);
                bf[np * 2][0] = r[0]; bf[np * 2][1] = r[1];
                bf[np * 2 + 1][0] = r[2]; bf[np * 2 + 1][1] = r[3];
            }
#pragma unroll
            for (int mi = 0; mi < 2; mi++)
#pragma unroll
                for (int ni = 0; ni < 4; ni++)
                    mma_f16(acc[mi][ni], af[mi], bf[ni]);
        }
        // no trailing barrier: next iteration's top barrier provides the WAR guard
    }

    // epilogue: fp16 store
    int col_in_frag = (lane & 3) * 2;
#pragma unroll
    for (int mi = 0; mi < 2; mi++) {
#pragma unroll
        for (int ni = 0; ni < 4; ni++) {
            int r0 = bm + warp_m * 32 + mi * 16 + (lane >> 2);
            int c0 = bn + warp_n * 32 + ni * 8 + col_in_frag;
            if (r0 < M) {
                __half2 h = __floats2half2_rn(acc[mi][ni][0], acc[mi][ni][1]);
                *(__half2*)(C16 + (size_t)r0 * N + c0) = h;
            }
            if (r0 + 8 < M) {
                __half2 h = __floats2half2_rn(acc[mi][ni][2], acc[mi][ni][3]);
                *(__half2*)(C16 + (size_t)(r0 + 8) * N + c0) = h;
            }
        }
    }
}

// ---------------------------------------------------------------------------
// Fused aggregation (fp16 gather, precomputed edge norms); fp16 output.
// ---------------------------------------------------------------------------
__global__ void __launch_bounds__(128)
fused_agg_kernel(const __half* __restrict__ h16, const int* __restrict__ cnt,
                 const int2* __restrict__ ell2, const float* __restrict__ bias,
                 __half* __restrict__ out16) {
    int grp  = threadIdx.x >> 6;          // 0..1
    int lane = threadIdx.x & 63;          // owns halves [lane*8, lane*8+8)
    int d = blockIdx.x * 2 + grp;

    int cd = cnt[d];
    float dd = rsqrtf((float)(cd + 1));
    int deg = min(cd, ELLW);
    const int2* erow = ell2 + (size_t)d * ELLW;

    float4 sp = ((const float4*)(h16 + (size_t)d * FDIM))[lane];
    const __half2* sh = (const __half2*)&sp;
    float sdd = dd * dd;
    float2 s0 = __half22float2(sh[0]);
    float2 s1 = __half22float2(sh[1]);
    float2 s2 = __half22float2(sh[2]);
    float2 s3 = __half22float2(sh[3]);
    float acc[8] = { s0.x * sdd, s0.y * sdd, s1.x * sdd, s1.y * sdd,
                     s2.x * sdd, s2.y * sdd, s3.x * sdd, s3.y * sdd };

#pragma unroll 2
    for (int j = 0; j < deg; j++) {
        int2 e = erow[j];                       // 8B broadcast: (src, nrm)
        int s = e.x;
        float nrm = __int_as_float(e.y);
        float4 p = ((const float4*)(h16 + (size_t)s * FDIM))[lane];
        const __half2* hp = (const __half2*)&p;
        float2 f0 = __half22float2(hp[0]);
        float2 f1 = __half22float2(hp[1]);
        float2 f2 = __half22float2(hp[2]);
        float2 f3 = __half22float2(hp[3]);
        acc[0] += f0.x * nrm; acc[1] += f0.y * nrm;
        acc[2] += f1.x * nrm; acc[3] += f1.y * nrm;
        acc[4] += f2.x * nrm; acc[5] += f2.y * nrm;
        acc[6] += f3.x * nrm; acc[7] += f3.y * nrm;
    }

    const float4* brow = (const float4*)bias;
    float4 b0 = brow[lane * 2];
    float4 b1 = brow[lane * 2 + 1];
    float v[8];
    v[0] = fmaxf(acc[0] + b0.x, 0.f); v[1] = fmaxf(acc[1] + b0.y, 0.f);
    v[2] = fmaxf(acc[2] + b0.z, 0.f); v[3] = fmaxf(acc[3] + b0.w, 0.f);
    v[4] = fmaxf(acc[4] + b1.x, 0.f); v[5] = fmaxf(acc[5] + b1.y, 0.f);
    v[6] = fmaxf(acc[6] + b1.z, 0.f); v[7] = fmaxf(acc[7] + b1.w, 0.f);

    __half2 h0 = __floats2half2_rn(v[0], v[1]);
    __half2 h1 = __floats2half2_rn(v[2], v[3]);
    __half2 h2 = __floats2half2_rn(v[4], v[5]);
    __half2 h3 = __floats2half2_rn(v[6], v[7]);
    uint4 u;
    u.x = *(uint32_t*)&h0; u.y = *(uint32_t*)&h1;
    u.z = *(uint32_t*)&h2; u.w = *(uint32_t*)&h3;
    ((uint4*)(out16 + (size_t)d * FDIM))[lane] = u;
}

// ---------------------------------------------------------------------------
// Pooling (batch sorted, fp16 input, fp32 accumulate):
// grid (graph, 4 strips), binary-search node range
// ---------------------------------------------------------------------------
__global__ void __launch_bounds__(128)
pool_kernel(const __half* __restrict__ h, const int* __restrict__ batch,
            float* __restrict__ pooled) {
    int g = blockIdx.x;
    int f = blockIdx.y * 128 + threadIdx.x;

    int lo = 0, hi = NNODES;
    while (lo < hi) { int mid = (lo + hi) >> 1; if (batch[mid] < g) lo = mid + 1; else hi = mid; }
    int beg = lo;
    hi = NNODES;
    while (lo < hi) { int mid = (lo + hi) >> 1; if (batch[mid] < g + 1) lo = mid + 1; else hi = mid; }
    int end = lo;

    float acc = 0.f;
    for (int n = beg; n < end; n++)
        acc += __half2float(h[(size_t)n * FDIM + f]);
    pooled[g * FDIM + f] = acc;
}

// ---------------------------------------------------------------------------
// Final small GEMM: out[64,128] = pooled[64,512] @ Wlin[512,128] + blin
// ---------------------------------------------------------------------------
__global__ void __launch_bounds__(128)
final_gemm_kernel(const float* __restrict__ pooled,
                  const float* __restrict__ Wlin,
                  const float* __restrict__ blin,
                  float* __restrict__ out) {
    __shared__ float p[FDIM];
    int g = blockIdx.x;
    int o = threadIdx.x;   // 128
    for (int k = o; k < FDIM; k += ODIM) p[k] = pooled[g * FDIM + k];
    __syncthreads();
    float acc = blin[o];
#pragma unroll 8
    for (int k = 0; k < FDIM; k++) acc += p[k] * Wlin[k * ODIM + o];
    out[g * ODIM + o] = acc;
}

// ---------------------------------------------------------------------------
// Launch
// ---------------------------------------------------------------------------
extern "C" void kernel_launch(void* const* d_in, const int* in_sizes, int n_in,
                              void* d_out, int out_size) {
    const float* x    = (const float*)d_in[0];
    const float* W1   = (const float*)d_in[1];
    const float* b1   = (const float*)d_in[2];
    const float* W2   = (const float*)d_in[3];
    const float* b2   = (const float*)d_in[4];
    const float* Wlin = (const float*)d_in[5];
    const float* blin = (const float*)d_in[6];
    const int* edge_index = (const int*)d_in[7];   // harness maps int64 -> int32
    const int* batch      = (const int*)d_in[8];

    const int* src = edge_index;
    const int* dst = edge_index + NEDGES;

    __half *x16, *w1t, *w2t, *a16, *b16;
    float *pooled_scratch;
    int *cnt;
    int2 *ell2;
    cudaGetSymbolAddress((void**)&x16, g_x16);
    cudaGetSymbolAddress((void**)&w1t, g_w1t);
    cudaGetSymbolAddress((void**)&w2t, g_w2t);
    cudaGetSymbolAddress((void**)&a16, g_a16);
    cudaGetSymbolAddress((void**)&b16, g_b16);
    cudaGetSymbolAddress((void**)&pooled_scratch, g_pooled);
    cudaGetSymbolAddress((void**)&cnt, g_cnt);
    cudaGetSymbolAddress((void**)&ell2, g_ell2);

    float* pooled;
    float* out2;
    if (out_size >= NGRAPH * FDIM + NGRAPH * ODIM) {
        pooled = (float*)d_out;
        out2   = (float*)d_out + NGRAPH * FDIM;
    } else {
        pooled = pooled_scratch;
        out2   = (float*)d_out;
    }

    // One-time setup: side stream + dynamic smem attribute.
    static cudaStream_t side = nullptr;
    static cudaEvent_t evFork = nullptr, evJoin = nullptr;
    static bool inited = false;
    if (!inited) {
        inited = true;
        cudaFuncSetAttribute(h16_gemm_kernel,
                             cudaFuncAttributeMaxDynamicSharedMemorySize, GEMM_SMEM);
        if (cudaStreamCreateWithFlags(&side, cudaStreamNonBlocking) != cudaSuccess)
            side = nullptr;
        if (side) {
            if (cudaEventCreateWithFlags(&evFork, cudaEventDisableTiming) != cudaSuccess ||
                cudaEventCreateWithFlags(&evJoin, cudaEventDisableTiming) != cudaSuccess)
                side = nullptr;
        }
    }

    dim3 gemm_grid(FDIM / 128, (NNODES + 127) / 128);

    // 1. convert + transpose + zero cnt (single launch)
    convert_zero_kernel<<<CONVERT_GRID, 256>>>(x, W1, W2, x16, w1t, w2t, cnt);

    if (side) {
        cudaEventRecord(evFork, 0);
        cudaStreamWaitEvent(side, evFork, 0);
        scatter_ell_kernel<<<(NEDGES + 255) / 256, 256, 0, side>>>(src, dst, cnt, ell2, NEDGES);
        nrm_kernel<<<(NNODES * ELLW + 255) / 256, 256, 0, side>>>(cnt, ell2);
        cudaEventRecord(evJoin, side);
        h16_gemm_kernel<<<gemm_grid, 512, GEMM_SMEM>>>(x16, w1t, a16, NNODES);
        cudaStreamWaitEvent(0, evJoin, 0);
    } else {
        scatter_ell_kernel<<<(NEDGES + 255) / 256, 256>>>(src, dst, cnt, ell2, NEDGES);
        nrm_kernel<<<(NNODES * ELLW + 255) / 256, 256>>>(cnt, ell2);
        h16_gemm_kernel<<<gemm_grid, 512, GEMM_SMEM>>>(x16, w1t, a16, NNODES);
    }

    // agg1 -> b16 (fp16)
    fused_agg_kernel<<<NNODES / 2, 128>>>(a16, cnt, ell2, b1, b16);

    // Layer 2: gemm (b16 -> a16), agg2 -> b16 (fp16, b16 free after gemm2)
    h16_gemm_kernel<<<gemm_grid, 512, GEMM_SMEM>>>(b16, w2t, a16, NNODES);
    fused_agg_kernel<<<NNODES / 2, 128>>>(a16, cnt, ell2, b2, b16);

    // Pool (fp16 in, fp32 out) + final linear
    {
        dim3 pg(NGRAPH, FDIM / 128);
        pool_kernel<<<pg, 128>>>(b16, batch, pooled);
    }
    final_gemm_kernel<<<NGRAPH, ODIM>>>(pooled, Wlin, blin, out2);
}